// round 12
// baseline (speedup 1.0000x reference)
#include <cuda_runtime.h>
#include <cuda_fp16.h>
#include <cstdint>

#define B_  2
#define S_  2048
#define D_  1024
#define H_  16
#define HD_ 64
#define M_  (B_ * S_)
#define NQKV 3072
#define QSCALE 0.18033688f   // (1/sqrt(64)) * log2(e)

// ---------------- scratch (static device globals) ---------------------------
__device__ __align__(16) __half g_xh[(size_t)M_ * D_];
__device__ __align__(16) __half g_wh[(size_t)4 * D_ * D_];   // Wq|Wk|Wv|Wo
__device__ __align__(16) __half g_qkv[(size_t)M_ * NQKV];
__device__ __align__(16) __half g_ah[(size_t)M_ * D_];
__device__ __align__(16) float  g_bias[NQKV];

// ---------------- PTX helpers ------------------------------------------------
__device__ __forceinline__ uint32_t smem_u32(const void* p) {
    uint32_t a;
    asm("{ .reg .u64 t; cvta.to.shared.u64 t, %1; cvt.u32.u64 %0, t; }" : "=r"(a) : "l"(p));
    return a;
}
__device__ __forceinline__ void ldsm4(uint32_t& r0, uint32_t& r1, uint32_t& r2, uint32_t& r3,
                                      uint32_t a) {
    asm volatile("ldmatrix.sync.aligned.m8n8.x4.shared.b16 {%0,%1,%2,%3}, [%4];"
                 : "=r"(r0), "=r"(r1), "=r"(r2), "=r"(r3) : "r"(a));
}
__device__ __forceinline__ void ldsm4t(uint32_t& r0, uint32_t& r1, uint32_t& r2, uint32_t& r3,
                                       uint32_t a) {
    asm volatile("ldmatrix.sync.aligned.m8n8.x4.trans.shared.b16 {%0,%1,%2,%3}, [%4];"
                 : "=r"(r0), "=r"(r1), "=r"(r2), "=r"(r3) : "r"(a));
}
__device__ __forceinline__ void mma16816(float* c, const uint32_t* a, const uint32_t* b) {
    asm volatile(
        "mma.sync.aligned.m16n8k16.row.col.f32.f16.f16.f32 "
        "{%0,%1,%2,%3}, {%4,%5,%6,%7}, {%8,%9}, {%0,%1,%2,%3};"
        : "+f"(c[0]), "+f"(c[1]), "+f"(c[2]), "+f"(c[3])
        : "r"(a[0]), "r"(a[1]), "r"(a[2]), "r"(a[3]), "r"(b[0]), "r"(b[1]));
}
#define CPA(s, g) asm volatile("cp.async.cg.shared.global [%0], [%1], 16;" :: "r"(s), "l"(g))
#define CPC()     asm volatile("cp.async.commit_group;" ::: "memory")
#define CPW1()    asm volatile("cp.async.wait_group 1;" ::: "memory")

__device__ __forceinline__ uint32_t packh2(float a, float b) {
    __half2 h = __floats2half2_rn(a, b);
    return *reinterpret_cast<uint32_t*>(&h);
}
__device__ __forceinline__ float ex2f(float x) {
    float y;
    asm("ex2.approx.ftz.f32 %0, %1;" : "=f"(y) : "f"(x));
    return y;
}
__device__ __forceinline__ uint32_t h2exp2u(uint32_t x) {
    uint32_t y;
    asm("ex2.approx.f16x2 %0, %1;" : "=r"(y) : "r"(x));
    return y;
}

// ---------------- fused convert (32 elems/thread) ----------------------------
#define XN ((size_t)M_ * D_)
#define WN ((size_t)D_ * D_)
#define CVT_TOTAL (XN + 4 * WN)     // 8388608 elems

__global__ __launch_bounds__(256)
void cvt_all(const float* __restrict__ x,
             const float* __restrict__ Wq, const float* __restrict__ Wk,
             const float* __restrict__ Wv, const float* __restrict__ Wo,
             const float* __restrict__ bq, const float* __restrict__ bk,
             const float* __restrict__ bv,
             __half* __restrict__ xh, __half* __restrict__ wh,
             float* __restrict__ bias) {
    size_t gid = (size_t)blockIdx.x * 256 + threadIdx.x;
    if (gid < NQKV) {
        int s = (int)(gid >> 10);
        const float* bs = (s == 0) ? bq : (s == 1) ? bk : bv;
        bias[gid] = bs[gid & 1023];
    }
    size_t i = gid * 32;   // 32 consecutive elems; array boundaries are 2^20-multiples
    const float* src;
    __half* dst;
    if (i < XN) {
        src = x + i; dst = xh + i;
    } else {
        size_t off = i - XN;
        int sel = (int)(off >> 20);
        size_t w = off & (WN - 1);
        src = ((sel == 0) ? Wq : (sel == 1) ? Wk : (sel == 2) ? Wv : Wo) + w;
        dst = wh + off;
    }
    float4 v[8];
#pragma unroll
    for (int j = 0; j < 8; ++j) v[j] = *(const float4*)(src + j * 4);
#pragma unroll
    for (int j = 0; j < 4; ++j) {
        __half2 h[4] = { __floats2half2_rn(v[2*j].x,   v[2*j].y),
                         __floats2half2_rn(v[2*j].z,   v[2*j].w),
                         __floats2half2_rn(v[2*j+1].x, v[2*j+1].y),
                         __floats2half2_rn(v[2*j+1].z, v[2*j+1].w) };
        *(uint4*)(dst + j * 8) = *(uint4*)h;
    }
}

// ---------------- fp16 HMMA GEMM (round-10 config: 128x128, 4 warps) ---------
#define GBM 128
#define GBN 128
#define GBK 64
#define GSTR 72
#define GBUF (GBM * GSTR)
#define GNKC (D_ / GBK)
#define GSMEM_BYTES (4 * GBUF * 2)

template<bool F16OUT, bool QKVMODE>
__global__ __launch_bounds__(128, 2)
void gemm_f16(const __half* __restrict__ A, const __half* __restrict__ Wt,
              const float* __restrict__ bias, void* __restrict__ Cout, int ldc) {
    extern __shared__ __align__(16) __half gsm[];
    __half* As = gsm;
    __half* Ws = gsm + 2 * GBUF;

    const int tid = threadIdx.x;
    const int wid = tid >> 5, lane = tid & 31;
    const int bm = blockIdx.y * GBM, bn = blockIdx.x * GBN;
    const int wm = (wid & 1) * 64, wn = (wid >> 1) * 64;
    const float osc = (QKVMODE && bn < 1024) ? QSCALE : 1.0f;

    float acc[4][8][4];
#pragma unroll
    for (int mt = 0; mt < 4; ++mt)
#pragma unroll
        for (int nt = 0; nt < 8; ++nt)
#pragma unroll
            for (int j = 0; j < 4; ++j) acc[mt][nt][j] = 0.0f;

#define GLOAD(kc, buf) do {                                                        \
    _Pragma("unroll")                                                              \
    for (int i = 0; i < 8; ++i) {                                                  \
        int idx = tid + i * 128; int r = idx >> 3, c = (idx & 7) * 8;              \
        CPA(smem_u32(&As[(buf) * GBUF + r * GSTR + c]),                            \
            A + (size_t)(bm + r) * D_ + (kc) * GBK + c);                           \
        CPA(smem_u32(&Ws[(buf) * GBUF + r * GSTR + c]),                            \
            Wt + (size_t)(bn + r) * D_ + (kc) * GBK + c);                          \
    }                                                                              \
} while (0)

    GLOAD(0, 0);
    CPC();
    int buf = 0;
    for (int kc = 0; kc < GNKC; ++kc) {
        if (kc + 1 < GNKC) GLOAD(kc + 1, buf ^ 1);
        CPC();
        CPW1();
        __syncthreads();
        const __half* Ab = As + buf * GBUF;
        const __half* Wb = Ws + buf * GBUF;
#pragma unroll
        for (int ks = 0; ks < 4; ++ks) {
            uint32_t af[4][4];
#pragma unroll
            for (int mt = 0; mt < 4; ++mt) {
                int row = wm + mt * 16 + (lane & 15);
                int col = ks * 16 + (lane >> 4) * 8;
                ldsm4(af[mt][0], af[mt][1], af[mt][2], af[mt][3],
                      smem_u32(&Ab[row * GSTR + col]));
            }
            uint32_t bf[8][2];
#pragma unroll
            for (int np = 0; np < 4; ++np) {
                int q = lane >> 3;
                int row = wn + np * 16 + (q >> 1) * 8 + (lane & 7);
                int col = ks * 16 + (q & 1) * 8;
                uint32_t r0, r1, r2, r3;
                ldsm4(r0, r1, r2, r3, smem_u32(&Wb[row * GSTR + col]));
                bf[np * 2][0] = r0; bf[np * 2][1] = r1;
                bf[np * 2 + 1][0] = r2; bf[np * 2 + 1][1] = r3;
            }
#pragma unroll
            for (int mt = 0; mt < 4; ++mt)
#pragma unroll
                for (int nt = 0; nt < 8; ++nt)
                    mma16816(acc[mt][nt], af[mt], bf[nt]);
        }
        __syncthreads();
        buf ^= 1;
    }
#undef GLOAD

#pragma unroll
    for (int mt = 0; mt < 4; ++mt) {
        int row = bm + wm + mt * 16 + (lane >> 2);
#pragma unroll
        for (int nt = 0; nt < 8; ++nt) {
            int col = bn + wn + nt * 8 + (lane & 3) * 2;
            float b0 = bias[col], b1 = bias[col + 1];
            float v0 = (acc[mt][nt][0] + b0) * osc, v1 = (acc[mt][nt][1] + b1) * osc;
            float v2 = (acc[mt][nt][2] + b0) * osc, v3 = (acc[mt][nt][3] + b1) * osc;
            if (F16OUT) {
                __half* base = (__half*)Cout;
                *(__half2*)(base + (size_t)row * ldc + col)       = __floats2half2_rn(v0, v1);
                *(__half2*)(base + (size_t)(row + 8) * ldc + col) = __floats2half2_rn(v2, v3);
            } else {
                float* base = (float*)Cout;
                *(float2*)(base + (size_t)row * ldc + col)       = make_float2(v0, v1);
                *(float2*)(base + (size_t)(row + 8) * ldc + col) = make_float2(v2, v3);
            }
        }
    }
}

// ---------------- flash attention (2-stage, f16x2 exp) -----------------------
#define AQ 128
#define AK 64
#define ASTR 72
#define A_QS   (AQ * ASTR)
#define A_KBUF (AK * ASTR)
#define ASMEM_BYTES ((A_QS + 4 * A_KBUF) * 2 + 2 * AK * 4)

__global__ __launch_bounds__(256)
void flash_f16(const __half* __restrict__ QKV, const int* __restrict__ mask,
               __half* __restrict__ O) {
    extern __shared__ __align__(16) __half asm_[];
    __half* Qs = asm_;
    __half* Ks = asm_ + A_QS;
    __half* Vs = asm_ + A_QS + 2 * A_KBUF;
    int*    msk = (int*)(asm_ + A_QS + 4 * A_KBUF);

    const int b = blockIdx.z, h = blockIdx.y, qt = blockIdx.x;
    const int tid = threadIdx.x, wid = tid >> 5, lane = tid & 31;

    const __half* Qg = QKV + (size_t)(b * S_ + qt * AQ) * NQKV + h * HD_;
    const __half* Kg = QKV + (size_t)(b * S_) * NQKV + 1024 + h * HD_;
    const __half* Vg = QKV + (size_t)(b * S_) * NQKV + 2048 + h * HD_;
    const int* mg = mask + b * S_;

#define KVLOAD(kt, buf) do {                                                          \
    _Pragma("unroll")                                                                 \
    for (int i = 0; i < 2; ++i) {                                                     \
        int idx = tid + i * 256; int r = idx >> 3, c = (idx & 7) * 8;                 \
        CPA(smem_u32(&Ks[(buf) * A_KBUF + r * ASTR + c]),                             \
            Kg + (size_t)((kt) * AK + r) * NQKV + c);                                 \
        CPA(smem_u32(&Vs[(buf) * A_KBUF + r * ASTR + c]),                             \
            Vg + (size_t)((kt) * AK + r) * NQKV + c);                                 \
    }                                                                                 \
    if (tid < 16) CPA(smem_u32(&msk[(buf) * AK + tid * 4]), mg + (kt) * AK + tid * 4);\
} while (0)

#pragma unroll
    for (int i = 0; i < 4; ++i) {
        int idx = tid + i * 256; int r = idx >> 3, c = (idx & 7) * 8;
        CPA(smem_u32(&Qs[r * ASTR + c]), Qg + (size_t)r * NQKV + c);
    }
    KVLOAD(0, 0);
    CPC();

    float m0 = -1e30f, m1 = -1e30f, l0 = 0.0f, l1 = 0.0f;
    float oacc[8][4];
#pragma unroll
    for (int nt = 0; nt < 8; ++nt)
#pragma unroll
        for (int j = 0; j < 4; ++j) oacc[nt][j] = 0.0f;
    uint32_t qf[4][4];

    int buf = 0;
    for (int kt = 0; kt < S_ / AK; ++kt) {
        if (kt + 1 < S_ / AK) KVLOAD(kt + 1, buf ^ 1);
        CPC();
        CPW1();
        __syncthreads();
        if (kt == 0) {
#pragma unroll
            for (int ks = 0; ks < 4; ++ks) {
                int row = wid * 16 + (lane & 15);
                int col = ks * 16 + (lane >> 4) * 8;
                ldsm4(qf[ks][0], qf[ks][1], qf[ks][2], qf[ks][3],
                      smem_u32(&Qs[row * ASTR + col]));
            }
        }

        // ---- S = Q K^T (log2 domain: q pre-scaled) ----
        float sacc[8][4];
#pragma unroll
        for (int nt = 0; nt < 8; ++nt)
#pragma unroll
            for (int j = 0; j < 4; ++j) sacc[nt][j] = 0.0f;
        const __half* Kb = Ks + buf * A_KBUF;
        const __half* Vb = Vs + buf * A_KBUF;
        const int* mb = msk + buf * AK;
#pragma unroll
        for (int ks = 0; ks < 4; ++ks) {
            uint32_t bfr[8][2];
#pragma unroll
            for (int np = 0; np < 4; ++np) {
                int q = lane >> 3;
                int row = np * 16 + (q >> 1) * 8 + (lane & 7);
                int col = ks * 16 + (q & 1) * 8;
                uint32_t r0, r1, r2, r3;
                ldsm4(r0, r1, r2, r3, smem_u32(&Kb[row * ASTR + col]));
                bfr[np * 2][0] = r0; bfr[np * 2][1] = r1;
                bfr[np * 2 + 1][0] = r2; bfr[np * 2 + 1][1] = r3;
            }
#pragma unroll
            for (int nt = 0; nt < 8; ++nt) mma16816(sacc[nt], qf[ks], bfr[nt]);
        }

        // ---- mask + online softmax (base 2, f16x2 exp) ----
        const int cc = (lane & 3) * 2;
#pragma unroll
        for (int nt = 0; nt < 8; ++nt) {
            int col = nt * 8 + cc;
            float ma  = mb[col]     ? 0.0f : -1e9f;
            float mbv = mb[col + 1] ? 0.0f : -1e9f;
            sacc[nt][0] += ma;  sacc[nt][1] += mbv;
            sacc[nt][2] += ma;  sacc[nt][3] += mbv;
        }
        float rx0 = -1e30f, rx1 = -1e30f;
#pragma unroll
        for (int nt = 0; nt < 8; ++nt) {
            rx0 = fmaxf(rx0, fmaxf(sacc[nt][0], sacc[nt][1]));
            rx1 = fmaxf(rx1, fmaxf(sacc[nt][2], sacc[nt][3]));
        }
        rx0 = fmaxf(rx0, __shfl_xor_sync(0xffffffffu, rx0, 1));
        rx0 = fmaxf(rx0, __shfl_xor_sync(0xffffffffu, rx0, 2));
        rx1 = fmaxf(rx1, __shfl_xor_sync(0xffffffffu, rx1, 1));
        rx1 = fmaxf(rx1, __shfl_xor_sync(0xffffffffu, rx1, 2));
        float mn0 = fmaxf(m0, rx0), mn1 = fmaxf(m1, rx1);
        float cor0 = ex2f(m0 - mn0), cor1 = ex2f(m1 - mn1);
        m0 = mn0; m1 = mn1;

        // p = 2^(s-m) in f16x2; ph doubles as the PV A-fragment
        uint32_t ph[8][2];
        float rs0 = 0.0f, rs1 = 0.0f;
#pragma unroll
        for (int nt = 0; nt < 8; ++nt) {
            ph[nt][0] = h2exp2u(packh2(sacc[nt][0] - mn0, sacc[nt][1] - mn0));
            ph[nt][1] = h2exp2u(packh2(sacc[nt][2] - mn1, sacc[nt][3] - mn1));
            float2 f0 = __half22float2(*(__half2*)&ph[nt][0]);
            float2 f1 = __half22float2(*(__half2*)&ph[nt][1]);
            rs0 += f0.x + f0.y;
            rs1 += f1.x + f1.y;
        }
        rs0 += __shfl_xor_sync(0xffffffffu, rs0, 1);
        rs0 += __shfl_xor_sync(0xffffffffu, rs0, 2);
        rs1 += __shfl_xor_sync(0xffffffffu, rs1, 1);
        rs1 += __shfl_xor_sync(0xffffffffu, rs1, 2);
        l0 = l0 * cor0 + rs0;
        l1 = l1 * cor1 + rs1;
#pragma unroll
        for (int nt = 0; nt < 8; ++nt) {
            oacc[nt][0] *= cor0; oacc[nt][1] *= cor0;
            oacc[nt][2] *= cor1; oacc[nt][3] *= cor1;
        }

        // ---- O += P V ----
#pragma unroll
        for (int ks = 0; ks < 4; ++ks) {
            uint32_t pa[4];
            pa[0] = ph[2 * ks][0];
            pa[1] = ph[2 * ks][1];
            pa[2] = ph[2 * ks + 1][0];
            pa[3] = ph[2 * ks + 1][1];
            uint32_t bfr[8][2];
#pragma unroll
            for (int np = 0; np < 4; ++np) {
                int q = lane >> 3;
                int row = ks * 16 + (q & 1) * 8 + (lane & 7);
                int col = np * 16 + (q >> 1) * 8;
                uint32_t r0, r1, r2, r3;
                ldsm4t(r0, r1, r2, r3, smem_u32(&Vb[row * ASTR + col]));
                bfr[np * 2][0] = r0; bfr[np * 2][1] = r1;
                bfr[np * 2 + 1][0] = r2; bfr[np * 2 + 1][1] = r3;
            }
#pragma unroll
            for (int nt = 0; nt < 8; ++nt) mma16816(oacc[nt], pa, bfr[nt]);
        }
        __syncthreads();
        buf ^= 1;
    }
#undef KVLOAD

    float li0 = 1.0f / l0, li1 = 1.0f / l1;
    __half* Og = O + (size_t)(b * S_ + qt * AQ + wid * 16) * D_ + h * HD_;
    int r0 = lane >> 2;
#pragma unroll
    for (int nt = 0; nt < 8; ++nt) {
        int col = nt * 8 + (lane & 3) * 2;
        *(__half2*)(Og + (size_t)r0 * D_ + col) =
            __floats2half2_rn(oacc[nt][0] * li0, oacc[nt][1] * li0);
        *(__half2*)(Og + (size_t)(r0 + 8) * D_ + col) =
            __floats2half2_rn(oacc[nt][2] * li1, oacc[nt][3] * li1);
    }
}

// ---------------------------- launch ---------------------------------------
extern "C" void kernel_launch(void* const* d_in, const int* in_sizes, int n_in,
                              void* d_out, int out_size) {
    const float* x    = (const float*)d_in[0];
    const int*   mask = (const int*)d_in[1];
    const float* Wq   = (const float*)d_in[2];
    const float* bq   = (const float*)d_in[3];
    const float* Wk   = (const float*)d_in[4];
    const float* bk   = (const float*)d_in[5];
    const float* Wv   = (const float*)d_in[6];
    const float* bv   = (const float*)d_in[7];
    const float* Wo   = (const float*)d_in[8];
    const float* bo   = (const float*)d_in[9];
    float* out = (float*)d_out;

    __half *xh, *wh, *qkv, *ah;
    float* bias;
    cudaGetSymbolAddress((void**)&xh,   g_xh);
    cudaGetSymbolAddress((void**)&wh,   g_wh);
    cudaGetSymbolAddress((void**)&qkv,  g_qkv);
    cudaGetSymbolAddress((void**)&ah,   g_ah);
    cudaGetSymbolAddress((void**)&bias, g_bias);

    cudaFuncSetAttribute(gemm_f16<true, true>,   cudaFuncAttributeMaxDynamicSharedMemorySize, GSMEM_BYTES);
    cudaFuncSetAttribute(gemm_f16<false, false>, cudaFuncAttributeMaxDynamicSharedMemorySize, GSMEM_BYTES);
    cudaFuncSetAttribute(flash_f16,              cudaFuncAttributeMaxDynamicSharedMemorySize, ASMEM_BYTES);

    cvt_all<<<(int)(CVT_TOTAL / 32 / 256), 256>>>(x, Wq, Wk, Wv, Wo, bq, bk, bv,
                                                  xh, wh, bias);
    dim3 qgrid(NQKV / GBN, M_ / GBM);   // (24, 32)
    gemm_f16<true, true><<<qgrid, 128, GSMEM_BYTES>>>(xh, wh, bias, qkv, NQKV);

    dim3 agrid(S_ / AQ, H_, B_);        // (16, 16, 2)
    flash_f16<<<agrid, 256, ASMEM_BYTES>>>(qkv, mask, ah);

    dim3 ogrid(D_ / GBN, M_ / GBM);     // (8, 32)
    gemm_f16<false, false><<<ogrid, 128, GSMEM_BYTES>>>(ah, wh + 3 * WN, bo, out, D_);
    (void)n_in; (void)in_sizes; (void)out_size;
}

// round 15
// speedup vs baseline: 1.0285x; 1.0285x over previous
#include <cuda_runtime.h>
#include <cuda_fp16.h>
#include <cstdint>

#define B_  2
#define S_  2048
#define D_  1024
#define H_  16
#define HD_ 64
#define M_  (B_ * S_)
#define NQKV 3072
#define QSCALE 0.18033688f   // (1/sqrt(64)) * log2(e)

// ---------------- scratch (static device globals) ---------------------------
__device__ __align__(16) __half g_xh[(size_t)M_ * D_];
__device__ __align__(16) __half g_wh[(size_t)4 * D_ * D_];   // Wq|Wk|Wv|Wo
__device__ __align__(16) __half g_qkv[(size_t)M_ * NQKV];
__device__ __align__(16) __half g_ah[(size_t)M_ * D_];
__device__ __align__(16) float  g_bias[NQKV];

// ---------------- PTX helpers ------------------------------------------------
__device__ __forceinline__ uint32_t smem_u32(const void* p) {
    uint32_t a;
    asm("{ .reg .u64 t; cvta.to.shared.u64 t, %1; cvt.u32.u64 %0, t; }" : "=r"(a) : "l"(p));
    return a;
}
__device__ __forceinline__ void ldsm4(uint32_t& r0, uint32_t& r1, uint32_t& r2, uint32_t& r3,
                                      uint32_t a) {
    asm volatile("ldmatrix.sync.aligned.m8n8.x4.shared.b16 {%0,%1,%2,%3}, [%4];"
                 : "=r"(r0), "=r"(r1), "=r"(r2), "=r"(r3) : "r"(a));
}
__device__ __forceinline__ void ldsm4t(uint32_t& r0, uint32_t& r1, uint32_t& r2, uint32_t& r3,
                                       uint32_t a) {
    asm volatile("ldmatrix.sync.aligned.m8n8.x4.trans.shared.b16 {%0,%1,%2,%3}, [%4];"
                 : "=r"(r0), "=r"(r1), "=r"(r2), "=r"(r3) : "r"(a));
}
__device__ __forceinline__ void mma16816(float* c, const uint32_t* a, const uint32_t* b) {
    asm volatile(
        "mma.sync.aligned.m16n8k16.row.col.f32.f16.f16.f32 "
        "{%0,%1,%2,%3}, {%4,%5,%6,%7}, {%8,%9}, {%0,%1,%2,%3};"
        : "+f"(c[0]), "+f"(c[1]), "+f"(c[2]), "+f"(c[3])
        : "r"(a[0]), "r"(a[1]), "r"(a[2]), "r"(a[3]), "r"(b[0]), "r"(b[1]));
}
#define CPA(s, g) asm volatile("cp.async.cg.shared.global [%0], [%1], 16;" :: "r"(s), "l"(g))
#define CPC()     asm volatile("cp.async.commit_group;" ::: "memory")
#define CPW1()    asm volatile("cp.async.wait_group 1;" ::: "memory")

__device__ __forceinline__ uint32_t packh2(float a, float b) {
    __half2 h = __floats2half2_rn(a, b);
    return *reinterpret_cast<uint32_t*>(&h);
}
__device__ __forceinline__ float ex2f(float x) {
    float y;
    asm("ex2.approx.ftz.f32 %0, %1;" : "=f"(y) : "f"(x));
    return y;
}

// ---------------- fused convert (32 elems/thread) ----------------------------
#define XN ((size_t)M_ * D_)
#define WN ((size_t)D_ * D_)
#define CVT_TOTAL (XN + 4 * WN)     // 8388608 elems

__global__ __launch_bounds__(256)
void cvt_all(const float* __restrict__ x,
             const float* __restrict__ Wq, const float* __restrict__ Wk,
             const float* __restrict__ Wv, const float* __restrict__ Wo,
             const float* __restrict__ bq, const float* __restrict__ bk,
             const float* __restrict__ bv,
             __half* __restrict__ xh, __half* __restrict__ wh,
             float* __restrict__ bias) {
    size_t gid = (size_t)blockIdx.x * 256 + threadIdx.x;
    if (gid < NQKV) {
        int s = (int)(gid >> 10);
        const float* bs = (s == 0) ? bq : (s == 1) ? bk : bv;
        bias[gid] = bs[gid & 1023];
    }
    size_t i = gid * 32;
    const float* src;
    __half* dst;
    if (i < XN) {
        src = x + i; dst = xh + i;
    } else {
        size_t off = i - XN;
        int sel = (int)(off >> 20);
        size_t w = off & (WN - 1);
        src = ((sel == 0) ? Wq : (sel == 1) ? Wk : (sel == 2) ? Wv : Wo) + w;
        dst = wh + off;
    }
    float4 v[8];
#pragma unroll
    for (int j = 0; j < 8; ++j) v[j] = *(const float4*)(src + j * 4);
#pragma unroll
    for (int j = 0; j < 4; ++j) {
        __half2 h[4] = { __floats2half2_rn(v[2*j].x,   v[2*j].y),
                         __floats2half2_rn(v[2*j].z,   v[2*j].w),
                         __floats2half2_rn(v[2*j+1].x, v[2*j+1].y),
                         __floats2half2_rn(v[2*j+1].z, v[2*j+1].w) };
        *(uint4*)(dst + j * 8) = *(uint4*)h;
    }
}

// ---------------- fp16 HMMA GEMM (round-10 config: 128x128, 4 warps) ---------
#define GBM 128
#define GBN 128
#define GBK 64
#define GSTR 72
#define GBUF (GBM * GSTR)
#define GNKC (D_ / GBK)
#define GSMEM_BYTES (4 * GBUF * 2)

template<bool F16OUT, bool QKVMODE>
__global__ __launch_bounds__(128, 2)
void gemm_f16(const __half* __restrict__ A, const __half* __restrict__ Wt,
              const float* __restrict__ bias, void* __restrict__ Cout, int ldc) {
    extern __shared__ __align__(16) __half gsm[];
    __half* As = gsm;
    __half* Ws = gsm + 2 * GBUF;

    const int tid = threadIdx.x;
    const int wid = tid >> 5, lane = tid & 31;
    const int bm = blockIdx.y * GBM, bn = blockIdx.x * GBN;
    const int wm = (wid & 1) * 64, wn = (wid >> 1) * 64;
    const float osc = (QKVMODE && bn < 1024) ? QSCALE : 1.0f;

    float acc[4][8][4];
#pragma unroll
    for (int mt = 0; mt < 4; ++mt)
#pragma unroll
        for (int nt = 0; nt < 8; ++nt)
#pragma unroll
            for (int j = 0; j < 4; ++j) acc[mt][nt][j] = 0.0f;

#define GLOAD(kc, buf) do {                                                        \
    _Pragma("unroll")                                                              \
    for (int i = 0; i < 8; ++i) {                                                  \
        int idx = tid + i * 128; int r = idx >> 3, c = (idx & 7) * 8;              \
        CPA(smem_u32(&As[(buf) * GBUF + r * GSTR + c]),                            \
            A + (size_t)(bm + r) * D_ + (kc) * GBK + c);                           \
        CPA(smem_u32(&Ws[(buf) * GBUF + r * GSTR + c]),                            \
            Wt + (size_t)(bn + r) * D_ + (kc) * GBK + c);                          \
    }                                                                              \
} while (0)

    GLOAD(0, 0);
    CPC();
    int buf = 0;
    for (int kc = 0; kc < GNKC; ++kc) {
        if (kc + 1 < GNKC) GLOAD(kc + 1, buf ^ 1);
        CPC();
        CPW1();
        __syncthreads();
        const __half* Ab = As + buf * GBUF;
        const __half* Wb = Ws + buf * GBUF;
#pragma unroll
        for (int ks = 0; ks < 4; ++ks) {
            uint32_t af[4][4];
#pragma unroll
            for (int mt = 0; mt < 4; ++mt) {
                int row = wm + mt * 16 + (lane & 15);
                int col = ks * 16 + (lane >> 4) * 8;
                ldsm4(af[mt][0], af[mt][1], af[mt][2], af[mt][3],
                      smem_u32(&Ab[row * GSTR + col]));
            }
            uint32_t bf[8][2];
#pragma unroll
            for (int np = 0; np < 4; ++np) {
                int q = lane >> 3;
                int row = wn + np * 16 + (q >> 1) * 8 + (lane & 7);
                int col = ks * 16 + (q & 1) * 8;
                uint32_t r0, r1, r2, r3;
                ldsm4(r0, r1, r2, r3, smem_u32(&Wb[row * GSTR + col]));
                bf[np * 2][0] = r0; bf[np * 2][1] = r1;
                bf[np * 2 + 1][0] = r2; bf[np * 2 + 1][1] = r3;
            }
#pragma unroll
            for (int mt = 0; mt < 4; ++mt)
#pragma unroll
                for (int nt = 0; nt < 8; ++nt)
                    mma16816(acc[mt][nt], af[mt], bf[nt]);
        }
        __syncthreads();
        buf ^= 1;
    }
#undef GLOAD

#pragma unroll
    for (int mt = 0; mt < 4; ++mt) {
        int row = bm + wm + mt * 16 + (lane >> 2);
#pragma unroll
        for (int nt = 0; nt < 8; ++nt) {
            int col = bn + wn + nt * 8 + (lane & 3) * 2;
            float b0 = bias[col], b1 = bias[col + 1];
            float v0 = (acc[mt][nt][0] + b0) * osc, v1 = (acc[mt][nt][1] + b1) * osc;
            float v2 = (acc[mt][nt][2] + b0) * osc, v3 = (acc[mt][nt][3] + b1) * osc;
            if (F16OUT) {
                __half* base = (__half*)Cout;
                *(__half2*)(base + (size_t)row * ldc + col)       = __floats2half2_rn(v0, v1);
                *(__half2*)(base + (size_t)(row + 8) * ldc + col) = __floats2half2_rn(v2, v3);
            } else {
                float* base = (float*)Cout;
                *(float2*)(base + (size_t)row * ldc + col)       = make_float2(v0, v1);
                *(float2*)(base + (size_t)(row + 8) * ldc + col) = make_float2(v2, v3);
            }
        }
    }
}

// ---------------- flash attention (fp32 ex2 + fast paths) --------------------
#define AQ 128
#define AK 64
#define ASTR 72
#define A_QS   (AQ * ASTR)
#define A_KBUF (AK * ASTR)
#define ASMEM_BYTES ((A_QS + 4 * A_KBUF) * 2 + 2 * AK * 4)

__global__ __launch_bounds__(256)
void flash_f16(const __half* __restrict__ QKV, const int* __restrict__ mask,
               __half* __restrict__ O) {
    extern __shared__ __align__(16) __half asm_[];
    __half* Qs = asm_;
    __half* Ks = asm_ + A_QS;
    __half* Vs = asm_ + A_QS + 2 * A_KBUF;
    int*    msk = (int*)(asm_ + A_QS + 4 * A_KBUF);

    const int b = blockIdx.z, h = blockIdx.y, qt = blockIdx.x;
    const int tid = threadIdx.x, wid = tid >> 5, lane = tid & 31;

    const __half* Qg = QKV + (size_t)(b * S_ + qt * AQ) * NQKV + h * HD_;
    const __half* Kg = QKV + (size_t)(b * S_) * NQKV + 1024 + h * HD_;
    const __half* Vg = QKV + (size_t)(b * S_) * NQKV + 2048 + h * HD_;
    const int* mg = mask + b * S_;

#define KVLOAD(kt, buf) do {                                                          \
    _Pragma("unroll")                                                                 \
    for (int i = 0; i < 2; ++i) {                                                     \
        int idx = tid + i * 256; int r = idx >> 3, c = (idx & 7) * 8;                 \
        CPA(smem_u32(&Ks[(buf) * A_KBUF + r * ASTR + c]),                             \
            Kg + (size_t)((kt) * AK + r) * NQKV + c);                                 \
        CPA(smem_u32(&Vs[(buf) * A_KBUF + r * ASTR + c]),                             \
            Vg + (size_t)((kt) * AK + r) * NQKV + c);                                 \
    }                                                                                 \
    if (tid < 16) CPA(smem_u32(&msk[(buf) * AK + tid * 4]), mg + (kt) * AK + tid * 4);\
} while (0)

#pragma unroll
    for (int i = 0; i < 4; ++i) {
        int idx = tid + i * 256; int r = idx >> 3, c = (idx & 7) * 8;
        CPA(smem_u32(&Qs[r * ASTR + c]), Qg + (size_t)r * NQKV + c);
    }
    KVLOAD(0, 0);
    CPC();

    float m0 = -1e30f, m1 = -1e30f, l0 = 0.0f, l1 = 0.0f;
    float oacc[8][4];
#pragma unroll
    for (int nt = 0; nt < 8; ++nt)
#pragma unroll
        for (int j = 0; j < 4; ++j) oacc[nt][j] = 0.0f;
    uint32_t qf[4][4];

    int buf = 0;
    for (int kt = 0; kt < S_ / AK; ++kt) {
        if (kt + 1 < S_ / AK) KVLOAD(kt + 1, buf ^ 1);
        CPC();
        CPW1();
        __syncthreads();
        if (kt == 0) {
#pragma unroll
            for (int ks = 0; ks < 4; ++ks) {
                int row = wid * 16 + (lane & 15);
                int col = ks * 16 + (lane >> 4) * 8;
                ldsm4(qf[ks][0], qf[ks][1], qf[ks][2], qf[ks][3],
                      smem_u32(&Qs[row * ASTR + col]));
            }
        }

        // ---- S = Q K^T (log2 domain: q pre-scaled) ----
        float sacc[8][4];
#pragma unroll
        for (int nt = 0; nt < 8; ++nt)
#pragma unroll
            for (int j = 0; j < 4; ++j) sacc[nt][j] = 0.0f;
        const __half* Kb = Ks + buf * A_KBUF;
        const __half* Vb = Vs + buf * A_KBUF;
        const int* mb = msk + buf * AK;
#pragma unroll
        for (int ks = 0; ks < 4; ++ks) {
            uint32_t bfr[8][2];
#pragma unroll
            for (int np = 0; np < 4; ++np) {
                int q = lane >> 3;
                int row = np * 16 + (q >> 1) * 8 + (lane & 7);
                int col = ks * 16 + (q & 1) * 8;
                uint32_t r0, r1, r2, r3;
                ldsm4(r0, r1, r2, r3, smem_u32(&Kb[row * ASTR + col]));
                bfr[np * 2][0] = r0; bfr[np * 2][1] = r1;
                bfr[np * 2 + 1][0] = r2; bfr[np * 2 + 1][1] = r3;
            }
#pragma unroll
            for (int nt = 0; nt < 8; ++nt) mma16816(sacc[nt], qf[ks], bfr[nt]);
        }

        // ---- mask (vote fast path: adding 0.0f is the identity) ----
        {
            int vm0 = mb[lane], vm1 = mb[lane + 32];
            bool allv = __all_sync(0xffffffffu, (vm0 != 0) && (vm1 != 0));
            if (!allv) {
                const int cc = (lane & 3) * 2;
#pragma unroll
                for (int nt = 0; nt < 8; ++nt) {
                    int col = nt * 8 + cc;
                    float ma  = mb[col]     ? 0.0f : -1e9f;
                    float mbv = mb[col + 1] ? 0.0f : -1e9f;
                    sacc[nt][0] += ma;  sacc[nt][1] += mbv;
                    sacc[nt][2] += ma;  sacc[nt][3] += mbv;
                }
            }
        }

        // ---- online softmax (base 2, fp32 ex2) ----
        float rx0 = -1e30f, rx1 = -1e30f;
#pragma unroll
        for (int nt = 0; nt < 8; ++nt) {
            rx0 = fmaxf(rx0, fmaxf(sacc[nt][0], sacc[nt][1]));
            rx1 = fmaxf(rx1, fmaxf(sacc[nt][2], sacc[nt][3]));
        }
        rx0 = fmaxf(rx0, __shfl_xor_sync(0xffffffffu, rx0, 1));
        rx0 = fmaxf(rx0, __shfl_xor_sync(0xffffffffu, rx0, 2));
        rx1 = fmaxf(rx1, __shfl_xor_sync(0xffffffffu, rx1, 1));
        rx1 = fmaxf(rx1, __shfl_xor_sync(0xffffffffu, rx1, 2));
        float mn0 = fmaxf(m0, rx0), mn1 = fmaxf(m1, rx1);
        bool needscale = (mn0 > m0) || (mn1 > m1);
        float cor0 = 1.0f, cor1 = 1.0f;
        if (needscale) { cor0 = ex2f(m0 - mn0); cor1 = ex2f(m1 - mn1); }
        m0 = mn0; m1 = mn1;

        float rs0 = 0.0f, rs1 = 0.0f;
#pragma unroll
        for (int nt = 0; nt < 8; ++nt) {
            sacc[nt][0] = ex2f(sacc[nt][0] - mn0);
            sacc[nt][1] = ex2f(sacc[nt][1] - mn0);
            sacc[nt][2] = ex2f(sacc[nt][2] - mn1);
            sacc[nt][3] = ex2f(sacc[nt][3] - mn1);
            rs0 += sacc[nt][0] + sacc[nt][1];
            rs1 += sacc[nt][2] + sacc[nt][3];
        }
        rs0 += __shfl_xor_sync(0xffffffffu, rs0, 1);
        rs0 += __shfl_xor_sync(0xffffffffu, rs0, 2);
        rs1 += __shfl_xor_sync(0xffffffffu, rs1, 1);
        rs1 += __shfl_xor_sync(0xffffffffu, rs1, 2);
        if (needscale) {
            l0 = l0 * cor0 + rs0;
            l1 = l1 * cor1 + rs1;
#pragma unroll
            for (int nt = 0; nt < 8; ++nt) {
                oacc[nt][0] *= cor0; oacc[nt][1] *= cor0;
                oacc[nt][2] *= cor1; oacc[nt][3] *= cor1;
            }
        } else {
            l0 += rs0;
            l1 += rs1;
        }

        // ---- O += P V ----
#pragma unroll
        for (int ks = 0; ks < 4; ++ks) {
            uint32_t pa[4];
            pa[0] = packh2(sacc[2 * ks][0],     sacc[2 * ks][1]);
            pa[1] = packh2(sacc[2 * ks][2],     sacc[2 * ks][3]);
            pa[2] = packh2(sacc[2 * ks + 1][0], sacc[2 * ks + 1][1]);
            pa[3] = packh2(sacc[2 * ks + 1][2], sacc[2 * ks + 1][3]);
            uint32_t bfr[8][2];
#pragma unroll
            for (int np = 0; np < 4; ++np) {
                int q = lane >> 3;
                int row = ks * 16 + (q & 1) * 8 + (lane & 7);
                int col = np * 16 + (q >> 1) * 8;
                uint32_t r0, r1, r2, r3;
                ldsm4t(r0, r1, r2, r3, smem_u32(&Vb[row * ASTR + col]));
                bfr[np * 2][0] = r0; bfr[np * 2][1] = r1;
                bfr[np * 2 + 1][0] = r2; bfr[np * 2 + 1][1] = r3;
            }
#pragma unroll
            for (int nt = 0; nt < 8; ++nt) mma16816(oacc[nt], pa, bfr[nt]);
        }
        __syncthreads();
        buf ^= 1;
    }
#undef KVLOAD

    float li0 = 1.0f / l0, li1 = 1.0f / l1;
    __half* Og = O + (size_t)(b * S_ + qt * AQ + wid * 16) * D_ + h * HD_;
    int r0 = lane >> 2;
#pragma unroll
    for (int nt = 0; nt < 8; ++nt) {
        int col = nt * 8 + (lane & 3) * 2;
        *(__half2*)(Og + (size_t)r0 * D_ + col) =
            __floats2half2_rn(oacc[nt][0] * li0, oacc[nt][1] * li0);
        *(__half2*)(Og + (size_t)(r0 + 8) * D_ + col) =
            __floats2half2_rn(oacc[nt][2] * li1, oacc[nt][3] * li1);
    }
}

// ---------------------------- launch ---------------------------------------
extern "C" void kernel_launch(void* const* d_in, const int* in_sizes, int n_in,
                              void* d_out, int out_size) {
    const float* x    = (const float*)d_in[0];
    const int*   mask = (const int*)d_in[1];
    const float* Wq   = (const float*)d_in[2];
    const float* bq   = (const float*)d_in[3];
    const float* Wk   = (const float*)d_in[4];
    const float* bk   = (const float*)d_in[5];
    const float* Wv   = (const float*)d_in[6];
    const float* bv   = (const float*)d_in[7];
    const float* Wo   = (const float*)d_in[8];
    const float* bo   = (const float*)d_in[9];
    float* out = (float*)d_out;

    __half *xh, *wh, *qkv, *ah;
    float* bias;
    cudaGetSymbolAddress((void**)&xh,   g_xh);
    cudaGetSymbolAddress((void**)&wh,   g_wh);
    cudaGetSymbolAddress((void**)&qkv,  g_qkv);
    cudaGetSymbolAddress((void**)&ah,   g_ah);
    cudaGetSymbolAddress((void**)&bias, g_bias);

    cudaFuncSetAttribute(gemm_f16<true, true>,   cudaFuncAttributeMaxDynamicSharedMemorySize, GSMEM_BYTES);
    cudaFuncSetAttribute(gemm_f16<false, false>, cudaFuncAttributeMaxDynamicSharedMemorySize, GSMEM_BYTES);
    cudaFuncSetAttribute(flash_f16,              cudaFuncAttributeMaxDynamicSharedMemorySize, ASMEM_BYTES);

    cvt_all<<<(int)(CVT_TOTAL / 32 / 256), 256>>>(x, Wq, Wk, Wv, Wo, bq, bk, bv,
                                                  xh, wh, bias);
    dim3 qgrid(NQKV / GBN, M_ / GBM);   // (24, 32)
    gemm_f16<true, true><<<qgrid, 128, GSMEM_BYTES>>>(xh, wh, bias, qkv, NQKV);

    dim3 agrid(S_ / AQ, H_, B_);        // (16, 16, 2)
    flash_f16<<<agrid, 256, ASMEM_BYTES>>>(qkv, mask, ah);

    dim3 ogrid(D_ / GBN, M_ / GBM);     // (8, 32)
    gemm_f16<false, false><<<ogrid, 128, GSMEM_BYTES>>>(ah, wh + 3 * WN, bo, out, D_);
    (void)n_in; (void)in_sizes; (void)out_size;
}

// round 16
// speedup vs baseline: 1.0525x; 1.0233x over previous
#include <cuda_runtime.h>
#include <cuda_fp16.h>
#include <cstdint>

#define B_  2
#define S_  2048
#define D_  1024
#define H_  16
#define HD_ 64
#define M_  (B_ * S_)
#define NQKV 3072
#define QSCALE 0.18033688f   // (1/sqrt(64)) * log2(e)

// ---------------- scratch (static device globals) ---------------------------
__device__ __align__(16) __half g_xh[(size_t)M_ * D_];
__device__ __align__(16) __half g_wh[(size_t)4 * D_ * D_];   // Wq|Wk|Wv|Wo
__device__ __align__(16) __half g_qkv[(size_t)M_ * NQKV];
__device__ __align__(16) __half g_ah[(size_t)M_ * D_];
__device__ __align__(16) float  g_bias[NQKV];

// ---------------- PTX helpers ------------------------------------------------
__device__ __forceinline__ uint32_t smem_u32(const void* p) {
    uint32_t a;
    asm("{ .reg .u64 t; cvta.to.shared.u64 t, %1; cvt.u32.u64 %0, t; }" : "=r"(a) : "l"(p));
    return a;
}
__device__ __forceinline__ void ldsm4(uint32_t& r0, uint32_t& r1, uint32_t& r2, uint32_t& r3,
                                      uint32_t a) {
    asm volatile("ldmatrix.sync.aligned.m8n8.x4.shared.b16 {%0,%1,%2,%3}, [%4];"
                 : "=r"(r0), "=r"(r1), "=r"(r2), "=r"(r3) : "r"(a));
}
__device__ __forceinline__ void ldsm4t(uint32_t& r0, uint32_t& r1, uint32_t& r2, uint32_t& r3,
                                       uint32_t a) {
    asm volatile("ldmatrix.sync.aligned.m8n8.x4.trans.shared.b16 {%0,%1,%2,%3}, [%4];"
                 : "=r"(r0), "=r"(r1), "=r"(r2), "=r"(r3) : "r"(a));
}
__device__ __forceinline__ void mma16816(float* c, const uint32_t* a, const uint32_t* b) {
    asm volatile(
        "mma.sync.aligned.m16n8k16.row.col.f32.f16.f16.f32 "
        "{%0,%1,%2,%3}, {%4,%5,%6,%7}, {%8,%9}, {%0,%1,%2,%3};"
        : "+f"(c[0]), "+f"(c[1]), "+f"(c[2]), "+f"(c[3])
        : "r"(a[0]), "r"(a[1]), "r"(a[2]), "r"(a[3]), "r"(b[0]), "r"(b[1]));
}
#define CPA(s, g) asm volatile("cp.async.cg.shared.global [%0], [%1], 16;" :: "r"(s), "l"(g))
#define CPC()     asm volatile("cp.async.commit_group;" ::: "memory")
#define CPW1()    asm volatile("cp.async.wait_group 1;" ::: "memory")

__device__ __forceinline__ uint32_t packh2(float a, float b) {
    __half2 h = __floats2half2_rn(a, b);
    return *reinterpret_cast<uint32_t*>(&h);
}
__device__ __forceinline__ float ex2f(float x) {
    float y;
    asm("ex2.approx.ftz.f32 %0, %1;" : "=f"(y) : "f"(x));
    return y;
}

// ---------------- fused convert (32 elems/thread) ----------------------------
#define XN ((size_t)M_ * D_)
#define WN ((size_t)D_ * D_)
#define CVT_TOTAL (XN + 4 * WN)     // 8388608 elems

__global__ __launch_bounds__(256)
void cvt_all(const float* __restrict__ x,
             const float* __restrict__ Wq, const float* __restrict__ Wk,
             const float* __restrict__ Wv, const float* __restrict__ Wo,
             const float* __restrict__ bq, const float* __restrict__ bk,
             const float* __restrict__ bv,
             __half* __restrict__ xh, __half* __restrict__ wh,
             float* __restrict__ bias) {
    size_t gid = (size_t)blockIdx.x * 256 + threadIdx.x;
    if (gid < NQKV) {
        int s = (int)(gid >> 10);
        const float* bs = (s == 0) ? bq : (s == 1) ? bk : bv;
        bias[gid] = bs[gid & 1023];
    }
    size_t i = gid * 32;
    const float* src;
    __half* dst;
    if (i < XN) {
        src = x + i; dst = xh + i;
    } else {
        size_t off = i - XN;
        int sel = (int)(off >> 20);
        size_t w = off & (WN - 1);
        src = ((sel == 0) ? Wq : (sel == 1) ? Wk : (sel == 2) ? Wv : Wo) + w;
        dst = wh + off;
    }
    float4 v[8];
#pragma unroll
    for (int j = 0; j < 8; ++j) v[j] = *(const float4*)(src + j * 4);
#pragma unroll
    for (int j = 0; j < 4; ++j) {
        __half2 h[4] = { __floats2half2_rn(v[2*j].x,   v[2*j].y),
                         __floats2half2_rn(v[2*j].z,   v[2*j].w),
                         __floats2half2_rn(v[2*j+1].x, v[2*j+1].y),
                         __floats2half2_rn(v[2*j+1].z, v[2*j+1].w) };
        *(uint4*)(dst + j * 8) = *(uint4*)h;
    }
}

// ---------------- fp16 HMMA GEMM (128x128, 4 warps, warp 64x64) --------------
#define GBM 128
#define GBN 128
#define GBK 64
#define GSTR 72
#define GBUF (GBM * GSTR)
#define GNKC (D_ / GBK)
#define GSMEM_BYTES (4 * GBUF * 2)

template<bool F16OUT, bool QKVMODE>
__global__ __launch_bounds__(128, 2)
void gemm_f16(const __half* __restrict__ A, const __half* __restrict__ Wt,
              const float* __restrict__ bias, void* __restrict__ Cout, int ldc) {
    extern __shared__ __align__(16) __half gsm[];
    __half* As = gsm;
    __half* Ws = gsm + 2 * GBUF;

    const int tid = threadIdx.x;
    const int wid = tid >> 5, lane = tid & 31;
    const int bm = blockIdx.y * GBM, bn = blockIdx.x * GBN;
    const int wm = (wid & 1) * 64, wn = (wid >> 1) * 64;
    const float osc = (QKVMODE && bn < 1024) ? QSCALE : 1.0f;

    float acc[4][8][4];
#pragma unroll
    for (int mt = 0; mt < 4; ++mt)
#pragma unroll
        for (int nt = 0; nt < 8; ++nt)
#pragma unroll
            for (int j = 0; j < 4; ++j) acc[mt][nt][j] = 0.0f;

#define GLOAD(kc, buf) do {                                                        \
    _Pragma("unroll")                                                              \
    for (int i = 0; i < 8; ++i) {                                                  \
        int idx = tid + i * 128; int r = idx >> 3, c = (idx & 7) * 8;              \
        CPA(smem_u32(&As[(buf) * GBUF + r * GSTR + c]),                            \
            A + (size_t)(bm + r) * D_ + (kc) * GBK + c);                           \
        CPA(smem_u32(&Ws[(buf) * GBUF + r * GSTR + c]),                            \
            Wt + (size_t)(bn + r) * D_ + (kc) * GBK + c);                          \
    }                                                                              \
} while (0)

    GLOAD(0, 0);
    CPC();
    int buf = 0;
    for (int kc = 0; kc < GNKC; ++kc) {
        if (kc + 1 < GNKC) GLOAD(kc + 1, buf ^ 1);
        CPC();
        CPW1();
        __syncthreads();
        const __half* Ab = As + buf * GBUF;
        const __half* Wb = Ws + buf * GBUF;
#pragma unroll
        for (int ks = 0; ks < 4; ++ks) {
            uint32_t af[4][4];
#pragma unroll
            for (int mt = 0; mt < 4; ++mt) {
                int row = wm + mt * 16 + (lane & 15);
                int col = ks * 16 + (lane >> 4) * 8;
                ldsm4(af[mt][0], af[mt][1], af[mt][2], af[mt][3],
                      smem_u32(&Ab[row * GSTR + col]));
            }
            uint32_t bf[8][2];
#pragma unroll
            for (int np = 0; np < 4; ++np) {
                int q = lane >> 3;
                int row = wn + np * 16 + (q >> 1) * 8 + (lane & 7);
                int col = ks * 16 + (q & 1) * 8;
                uint32_t r0, r1, r2, r3;
                ldsm4(r0, r1, r2, r3, smem_u32(&Wb[row * GSTR + col]));
                bf[np * 2][0] = r0; bf[np * 2][1] = r1;
                bf[np * 2 + 1][0] = r2; bf[np * 2 + 1][1] = r3;
            }
#pragma unroll
            for (int mt = 0; mt < 4; ++mt)
#pragma unroll
                for (int nt = 0; nt < 8; ++nt)
                    mma16816(acc[mt][nt], af[mt], bf[nt]);
        }
        __syncthreads();
        buf ^= 1;
    }
#undef GLOAD

#pragma unroll
    for (int mt = 0; mt < 4; ++mt) {
        int row = bm + wm + mt * 16 + (lane >> 2);
#pragma unroll
        for (int nt = 0; nt < 8; ++nt) {
            int col = bn + wn + nt * 8 + (lane & 3) * 2;
            float b0 = bias[col], b1 = bias[col + 1];
            float v0 = (acc[mt][nt][0] + b0) * osc, v1 = (acc[mt][nt][1] + b1) * osc;
            float v2 = (acc[mt][nt][2] + b0) * osc, v3 = (acc[mt][nt][3] + b1) * osc;
            if (F16OUT) {
                __half* base = (__half*)Cout;
                *(__half2*)(base + (size_t)row * ldc + col)       = __floats2half2_rn(v0, v1);
                *(__half2*)(base + (size_t)(row + 8) * ldc + col) = __floats2half2_rn(v2, v3);
            } else {
                float* base = (float*)Cout;
                *(float2*)(base + (size_t)row * ldc + col)       = make_float2(v0, v1);
                *(float2*)(base + (size_t)(row + 8) * ldc + col) = make_float2(v2, v3);
            }
        }
    }
}

// ---------------- flash attention (fp32 ex2 + fast paths; batch as arg) ------
#define AQ 128
#define AK 64
#define ASTR 72
#define A_QS   (AQ * ASTR)
#define A_KBUF (AK * ASTR)
#define ASMEM_BYTES ((A_QS + 4 * A_KBUF) * 2 + 2 * AK * 4)

__global__ __launch_bounds__(256)
void flash_f16(const __half* __restrict__ QKV, const int* __restrict__ mask,
               __half* __restrict__ O, int bb) {
    extern __shared__ __align__(16) __half asm_[];
    __half* Qs = asm_;
    __half* Ks = asm_ + A_QS;
    __half* Vs = asm_ + A_QS + 2 * A_KBUF;
    int*    msk = (int*)(asm_ + A_QS + 4 * A_KBUF);

    const int b = bb, h = blockIdx.y, qt = blockIdx.x;
    const int tid = threadIdx.x, wid = tid >> 5, lane = tid & 31;

    const __half* Qg = QKV + (size_t)(b * S_ + qt * AQ) * NQKV + h * HD_;
    const __half* Kg = QKV + (size_t)(b * S_) * NQKV + 1024 + h * HD_;
    const __half* Vg = QKV + (size_t)(b * S_) * NQKV + 2048 + h * HD_;
    const int* mg = mask + b * S_;

#define KVLOAD(kt, buf) do {                                                          \
    _Pragma("unroll")                                                                 \
    for (int i = 0; i < 2; ++i) {                                                     \
        int idx = tid + i * 256; int r = idx >> 3, c = (idx & 7) * 8;                 \
        CPA(smem_u32(&Ks[(buf) * A_KBUF + r * ASTR + c]),                             \
            Kg + (size_t)((kt) * AK + r) * NQKV + c);                                 \
        CPA(smem_u32(&Vs[(buf) * A_KBUF + r * ASTR + c]),                             \
            Vg + (size_t)((kt) * AK + r) * NQKV + c);                                 \
    }                                                                                 \
    if (tid < 16) CPA(smem_u32(&msk[(buf) * AK + tid * 4]), mg + (kt) * AK + tid * 4);\
} while (0)

#pragma unroll
    for (int i = 0; i < 4; ++i) {
        int idx = tid + i * 256; int r = idx >> 3, c = (idx & 7) * 8;
        CPA(smem_u32(&Qs[r * ASTR + c]), Qg + (size_t)r * NQKV + c);
    }
    KVLOAD(0, 0);
    CPC();

    float m0 = -1e30f, m1 = -1e30f, l0 = 0.0f, l1 = 0.0f;
    float oacc[8][4];
#pragma unroll
    for (int nt = 0; nt < 8; ++nt)
#pragma unroll
        for (int j = 0; j < 4; ++j) oacc[nt][j] = 0.0f;
    uint32_t qf[4][4];

    int buf = 0;
    for (int kt = 0; kt < S_ / AK; ++kt) {
        if (kt + 1 < S_ / AK) KVLOAD(kt + 1, buf ^ 1);
        CPC();
        CPW1();
        __syncthreads();
        if (kt == 0) {
#pragma unroll
            for (int ks = 0; ks < 4; ++ks) {
                int row = wid * 16 + (lane & 15);
                int col = ks * 16 + (lane >> 4) * 8;
                ldsm4(qf[ks][0], qf[ks][1], qf[ks][2], qf[ks][3],
                      smem_u32(&Qs[row * ASTR + col]));
            }
        }

        // ---- S = Q K^T (log2 domain: q pre-scaled) ----
        float sacc[8][4];
#pragma unroll
        for (int nt = 0; nt < 8; ++nt)
#pragma unroll
            for (int j = 0; j < 4; ++j) sacc[nt][j] = 0.0f;
        const __half* Kb = Ks + buf * A_KBUF;
        const __half* Vb = Vs + buf * A_KBUF;
        const int* mb = msk + buf * AK;
#pragma unroll
        for (int ks = 0; ks < 4; ++ks) {
            uint32_t bfr[8][2];
#pragma unroll
            for (int np = 0; np < 4; ++np) {
                int q = lane >> 3;
                int row = np * 16 + (q >> 1) * 8 + (lane & 7);
                int col = ks * 16 + (q & 1) * 8;
                uint32_t r0, r1, r2, r3;
                ldsm4(r0, r1, r2, r3, smem_u32(&Kb[row * ASTR + col]));
                bfr[np * 2][0] = r0; bfr[np * 2][1] = r1;
                bfr[np * 2 + 1][0] = r2; bfr[np * 2 + 1][1] = r3;
            }
#pragma unroll
            for (int nt = 0; nt < 8; ++nt) mma16816(sacc[nt], qf[ks], bfr[nt]);
        }

        // ---- mask (vote fast path: adding 0.0f is the identity) ----
        {
            int vm0 = mb[lane], vm1 = mb[lane + 32];
            bool allv = __all_sync(0xffffffffu, (vm0 != 0) && (vm1 != 0));
            if (!allv) {
                const int cc = (lane & 3) * 2;
#pragma unroll
                for (int nt = 0; nt < 8; ++nt) {
                    int col = nt * 8 + cc;
                    float ma  = mb[col]     ? 0.0f : -1e9f;
                    float mbv = mb[col + 1] ? 0.0f : -1e9f;
                    sacc[nt][0] += ma;  sacc[nt][1] += mbv;
                    sacc[nt][2] += ma;  sacc[nt][3] += mbv;
                }
            }
        }

        // ---- online softmax (base 2, fp32 ex2) ----
        float rx0 = -1e30f, rx1 = -1e30f;
#pragma unroll
        for (int nt = 0; nt < 8; ++nt) {
            rx0 = fmaxf(rx0, fmaxf(sacc[nt][0], sacc[nt][1]));
            rx1 = fmaxf(rx1, fmaxf(sacc[nt][2], sacc[nt][3]));
        }
        rx0 = fmaxf(rx0, __shfl_xor_sync(0xffffffffu, rx0, 1));
        rx0 = fmaxf(rx0, __shfl_xor_sync(0xffffffffu, rx0, 2));
        rx1 = fmaxf(rx1, __shfl_xor_sync(0xffffffffu, rx1, 1));
        rx1 = fmaxf(rx1, __shfl_xor_sync(0xffffffffu, rx1, 2));
        float mn0 = fmaxf(m0, rx0), mn1 = fmaxf(m1, rx1);
        bool needscale = (mn0 > m0) || (mn1 > m1);
        float cor0 = 1.0f, cor1 = 1.0f;
        if (needscale) { cor0 = ex2f(m0 - mn0); cor1 = ex2f(m1 - mn1); }
        m0 = mn0; m1 = mn1;

        float rs0 = 0.0f, rs1 = 0.0f;
#pragma unroll
        for (int nt = 0; nt < 8; ++nt) {
            sacc[nt][0] = ex2f(sacc[nt][0] - mn0);
            sacc[nt][1] = ex2f(sacc[nt][1] - mn0);
            sacc[nt][2] = ex2f(sacc[nt][2] - mn1);
            sacc[nt][3] = ex2f(sacc[nt][3] - mn1);
            rs0 += sacc[nt][0] + sacc[nt][1];
            rs1 += sacc[nt][2] + sacc[nt][3];
        }
        rs0 += __shfl_xor_sync(0xffffffffu, rs0, 1);
        rs0 += __shfl_xor_sync(0xffffffffu, rs0, 2);
        rs1 += __shfl_xor_sync(0xffffffffu, rs1, 1);
        rs1 += __shfl_xor_sync(0xffffffffu, rs1, 2);
        if (needscale) {
            l0 = l0 * cor0 + rs0;
            l1 = l1 * cor1 + rs1;
#pragma unroll
            for (int nt = 0; nt < 8; ++nt) {
                oacc[nt][0] *= cor0; oacc[nt][1] *= cor0;
                oacc[nt][2] *= cor1; oacc[nt][3] *= cor1;
            }
        } else {
            l0 += rs0;
            l1 += rs1;
        }

        // ---- O += P V ----
#pragma unroll
        for (int ks = 0; ks < 4; ++ks) {
            uint32_t pa[4];
            pa[0] = packh2(sacc[2 * ks][0],     sacc[2 * ks][1]);
            pa[1] = packh2(sacc[2 * ks][2],     sacc[2 * ks][3]);
            pa[2] = packh2(sacc[2 * ks + 1][0], sacc[2 * ks + 1][1]);
            pa[3] = packh2(sacc[2 * ks + 1][2], sacc[2 * ks + 1][3]);
            uint32_t bfr[8][2];
#pragma unroll
            for (int np = 0; np < 4; ++np) {
                int q = lane >> 3;
                int row = ks * 16 + (q & 1) * 8 + (lane & 7);
                int col = np * 16 + (q >> 1) * 8;
                uint32_t r0, r1, r2, r3;
                ldsm4t(r0, r1, r2, r3, smem_u32(&Vb[row * ASTR + col]));
                bfr[np * 2][0] = r0; bfr[np * 2][1] = r1;
                bfr[np * 2 + 1][0] = r2; bfr[np * 2 + 1][1] = r3;
            }
#pragma unroll
            for (int nt = 0; nt < 8; ++nt) mma16816(oacc[nt], pa, bfr[nt]);
        }
        __syncthreads();
        buf ^= 1;
    }
#undef KVLOAD

    float li0 = 1.0f / l0, li1 = 1.0f / l1;
    __half* Og = O + (size_t)(b * S_ + qt * AQ + wid * 16) * D_ + h * HD_;
    int r0 = lane >> 2;
#pragma unroll
    for (int nt = 0; nt < 8; ++nt) {
        int col = nt * 8 + (lane & 3) * 2;
        *(__half2*)(Og + (size_t)r0 * D_ + col) =
            __floats2half2_rn(oacc[nt][0] * li0, oacc[nt][1] * li0);
        *(__half2*)(Og + (size_t)(r0 + 8) * D_ + col) =
            __floats2half2_rn(oacc[nt][2] * li1, oacc[nt][3] * li1);
    }
}

// ---------------------------- launch ---------------------------------------
extern "C" void kernel_launch(void* const* d_in, const int* in_sizes, int n_in,
                              void* d_out, int out_size) {
    const float* x    = (const float*)d_in[0];
    const int*   mask = (const int*)d_in[1];
    const float* Wq   = (const float*)d_in[2];
    const float* bq   = (const float*)d_in[3];
    const float* Wk   = (const float*)d_in[4];
    const float* bk   = (const float*)d_in[5];
    const float* Wv   = (const float*)d_in[6];
    const float* bv   = (const float*)d_in[7];
    const float* Wo   = (const float*)d_in[8];
    const float* bo   = (const float*)d_in[9];
    float* out = (float*)d_out;

    __half *xh, *wh, *qkv, *ah;
    float* bias;
    cudaGetSymbolAddress((void**)&xh,   g_xh);
    cudaGetSymbolAddress((void**)&wh,   g_wh);
    cudaGetSymbolAddress((void**)&qkv,  g_qkv);
    cudaGetSymbolAddress((void**)&ah,   g_ah);
    cudaGetSymbolAddress((void**)&bias, g_bias);

    cudaFuncSetAttribute(gemm_f16<true, true>,   cudaFuncAttributeMaxDynamicSharedMemorySize, GSMEM_BYTES);
    cudaFuncSetAttribute(gemm_f16<false, false>, cudaFuncAttributeMaxDynamicSharedMemorySize, GSMEM_BYTES);
    cudaFuncSetAttribute(flash_f16,              cudaFuncAttributeMaxDynamicSharedMemorySize, ASMEM_BYTES);

    // side stream + events, created once (host-side resources only; the
    // captured work sequence is identical on every call)
    static cudaStream_t s1 = nullptr;
    static cudaEvent_t evFork = nullptr, evJoin = nullptr;
    if (s1 == nullptr) {
        cudaStreamCreateWithFlags(&s1, cudaStreamNonBlocking);
        cudaEventCreateWithFlags(&evFork, cudaEventDisableTiming);
        cudaEventCreateWithFlags(&evJoin, cudaEventDisableTiming);
    }

    const size_t HB_X   = (size_t)S_ * D_;     // per-batch rows of x/ah/out
    const size_t HB_QKV = (size_t)S_ * NQKV;   // per-batch rows of qkv

    // 1) convert everything (main stream)
    cvt_all<<<(int)(CVT_TOTAL / 32 / 256), 256>>>(x, Wq, Wk, Wv, Wo, bq, bk, bv,
                                                  xh, wh, bias);

    dim3 qgrid(NQKV / GBN, S_ / GBM);   // (24, 16) per batch half
    dim3 agrid(S_ / AQ, H_, 1);         // (16, 16) per batch half
    dim3 ogrid(D_ / GBN, S_ / GBM);     // (8, 16)  per batch half

    // 2) qkv for batch 0 (main)
    gemm_f16<true, true><<<qgrid, 128, GSMEM_BYTES>>>(xh, wh, bias, qkv, NQKV);

    // fork: s1 handles batch 0's flash + oproj
    cudaEventRecord(evFork, 0);
    cudaStreamWaitEvent(s1, evFork, 0);

    // s1:   flash(b0)           || main: qkv(b1)
    flash_f16<<<agrid, 256, ASMEM_BYTES, s1>>>(qkv, mask, ah, 0);
    gemm_f16<true, true><<<qgrid, 128, GSMEM_BYTES>>>(xh + HB_X, wh, bias,
                                                      qkv + HB_QKV, NQKV);

    // s1:   oproj(b0)           || main: flash(b1)
    gemm_f16<false, false><<<ogrid, 128, GSMEM_BYTES, s1>>>(ah, wh + 3 * WN, bo, out, D_);
    flash_f16<<<agrid, 256, ASMEM_BYTES>>>(qkv, mask, ah, 1);

    // main: oproj(b1)
    gemm_f16<false, false><<<ogrid, 128, GSMEM_BYTES>>>(ah + HB_X, wh + 3 * WN, bo,
                                                        out + HB_X, D_);

    // join: main waits for s1's oproj(b0)
    cudaEventRecord(evJoin, s1);
    cudaStreamWaitEvent(0, evJoin, 0);
    (void)n_in; (void)in_sizes; (void)out_size;
}